// round 8
// baseline (speedup 1.0000x reference)
#include <cuda_runtime.h>
#include <cuda_bf16.h>
#include <stdint.h>

// R8: 2D warp tiling (4 m-groups x 2 key-groups) to halve K/V LDSM traffic.
// Epilogue reduces key-partial O/Z across warp pairs through smem.

static constexpr int BATCH = 16;
static constexpr int LSEQ  = 2048;
static constexpr int DHEAD = 128;
static constexpr int TQ    = 128;
static constexpr int TKN   = 64;
static constexpr int NKT   = LSEQ / TKN;   // 32

static constexpr int PAD   = 136;
static constexpr int QT_BYTES = TQ  * PAD * 2;
static constexpr int KT_BYTES = TKN * PAD * 2;
static constexpr int SQH = 0;
static constexpr int SQL = QT_BYTES;
static constexpr int SBUF0 = 2 * QT_BYTES;
static constexpr int BUF_STRIDE = 4 * KT_BYTES;
static constexpr int OKH = 0, OKL = KT_BYTES, OVH = 2 * KT_BYTES, OVL = 3 * KT_BYTES;
static constexpr int SMEM_BYTES = SBUF0 + 2 * BUF_STRIDE;  // 208896

__device__ __align__(16) __nv_bfloat16 g_qh[(size_t)BATCH * LSEQ * DHEAD];
__device__ __align__(16) __nv_bfloat16 g_ql[(size_t)BATCH * LSEQ * DHEAD];
__device__ __align__(16) __nv_bfloat16 g_kh[(size_t)BATCH * LSEQ * DHEAD];
__device__ __align__(16) __nv_bfloat16 g_kl[(size_t)BATCH * LSEQ * DHEAD];
__device__ __align__(16) __nv_bfloat16 g_vh[(size_t)BATCH * LSEQ * DHEAD];
__device__ __align__(16) __nv_bfloat16 g_vl[(size_t)BATCH * LSEQ * DHEAD];

// ---------------- helpers ----------------
__device__ __forceinline__ uint32_t smem_u32(const void* p) {
    uint32_t a;
    asm("{ .reg .u64 t; cvta.to.shared.u64 t, %1; cvt.u32.u64 %0, t; }" : "=r"(a) : "l"(p));
    return a;
}
__device__ __forceinline__ uint32_t pack2(__nv_bfloat16 a, __nv_bfloat16 b) {
    return (uint32_t)__bfloat16_as_ushort(a) | ((uint32_t)__bfloat16_as_ushort(b) << 16);
}
__device__ __forceinline__ void ldsm_x4(uint32_t* r, uint32_t addr) {
    asm volatile("ldmatrix.sync.aligned.m8n8.x4.shared.b16 {%0,%1,%2,%3}, [%4];"
                 : "=r"(r[0]), "=r"(r[1]), "=r"(r[2]), "=r"(r[3]) : "r"(addr));
}
__device__ __forceinline__ void ldsm_x4_t(uint32_t* r, uint32_t addr) {
    asm volatile("ldmatrix.sync.aligned.m8n8.x4.trans.shared.b16 {%0,%1,%2,%3}, [%4];"
                 : "=r"(r[0]), "=r"(r[1]), "=r"(r[2]), "=r"(r[3]) : "r"(addr));
}
__device__ __forceinline__ void mma16816(float* d, const uint32_t* a, const uint32_t* b) {
    asm volatile("mma.sync.aligned.m16n8k16.row.col.f32.bf16.bf16.f32 "
                 "{%0,%1,%2,%3}, {%4,%5,%6,%7}, {%8,%9}, {%0,%1,%2,%3};"
                 : "+f"(d[0]), "+f"(d[1]), "+f"(d[2]), "+f"(d[3])
                 : "r"(a[0]), "r"(a[1]), "r"(a[2]), "r"(a[3]), "r"(b[0]), "r"(b[1]));
}
__device__ __forceinline__ void cp16(uint32_t dst, const void* src) {
    asm volatile("cp.async.cg.shared.global [%0], [%1], 16;" :: "r"(dst), "l"(src));
}
#define CP_COMMIT() asm volatile("cp.async.commit_group;" ::: "memory")

__device__ __forceinline__ void stage64(uint32_t dstb, const __nv_bfloat16* __restrict__ g, int tid) {
    #pragma unroll
    for (int i = 0; i < 4; ++i) {
        int idx = tid + i * 256;
        int row = idx >> 4, c = idx & 15;
        cp16(dstb + row * (PAD * 2) + c * 16, g + row * DHEAD + c * 8);
    }
}
__device__ __forceinline__ void stage128(uint32_t dstb, const __nv_bfloat16* __restrict__ g, int tid) {
    #pragma unroll
    for (int i = 0; i < 8; ++i) {
        int idx = tid + i * 256;
        int row = idx >> 4, c = idx & 15;
        cp16(dstb + row * (PAD * 2) + c * 16, g + row * DHEAD + c * 8);
    }
}

// -------- prep: fp32 -> bf16 hi/lo --------
__device__ __forceinline__ void split4(float4 f, __nv_bfloat16* hi, __nv_bfloat16* lo, size_t i4) {
    __nv_bfloat16 h0 = __float2bfloat16_rn(f.x), h1 = __float2bfloat16_rn(f.y);
    __nv_bfloat16 h2 = __float2bfloat16_rn(f.z), h3 = __float2bfloat16_rn(f.w);
    *reinterpret_cast<uint2*>(hi + 4 * i4) = make_uint2(pack2(h0, h1), pack2(h2, h3));
    *reinterpret_cast<uint2*>(lo + 4 * i4) = make_uint2(
        pack2(__float2bfloat16_rn(f.x - __bfloat162float(h0)), __float2bfloat16_rn(f.y - __bfloat162float(h1))),
        pack2(__float2bfloat16_rn(f.z - __bfloat162float(h2)), __float2bfloat16_rn(f.w - __bfloat162float(h3))));
}
__global__ void prep_split(const float* __restrict__ q, const float* __restrict__ k,
                           const float* __restrict__ v) {
    size_t i = (size_t)blockIdx.x * blockDim.x + threadIdx.x;
    split4(reinterpret_cast<const float4*>(q)[i], g_qh, g_ql, i);
    split4(reinterpret_cast<const float4*>(k)[i], g_kh, g_kl, i);
    split4(reinterpret_cast<const float4*>(v)[i], g_vh, g_vl, i);
}

// -------- fused attention + layernorm --------
__global__ void __launch_bounds__(256, 1)
fmha_ln_hmma(const float* __restrict__ MASK, const float* __restrict__ GAMMA,
             const float* __restrict__ BETA, float* __restrict__ OUT) {
    extern __shared__ char sm[];
    const int tid = threadIdx.x;
    const int w   = tid >> 5;
    const int l   = tid & 31;
    const int b   = blockIdx.y;
    const int q0  = blockIdx.x * TQ;

    const int mg  = w & 3;          // m-group: rows 32*mg .. +31 (two m16 A-tiles)
    const int ng  = w >> 2;         // key-group: keys 32*ng .. +31 within each tile
    const int m0  = mg * 32;
    const int qr  = l >> 2;
    const int qc2 = (l & 3) * 2;

    const uint32_t smb = smem_u32(sm);
    const int lr = l & 7, g = l >> 3;

    // A-frag offsets for the two m16 tiles (x4 non-trans)
    uint32_t a_off[2];
    #pragma unroll
    for (int at = 0; at < 2; ++at)
        a_off[at] = (uint32_t)((m0 + 16 * at + lr + ((g & 1) << 3)) * PAD + ((g >> 1) << 3)) * 2;
    // K B-frag x4 (n-pair x k16), rows = warp's key slice
    const uint32_t kb4_off = (uint32_t)((32 * ng + lr + ((g >> 1) << 3)) * PAD + ((g & 1) << 3)) * 2;
    // V B-frag x4 trans (k16 x d-pair), rows = warp's key slice
    const uint32_t vb4_off = (uint32_t)((32 * ng + lr + ((g & 1) << 3)) * PAD + ((g >> 1) << 3)) * 2;

    const size_t qgbase = ((size_t)(b * LSEQ + q0)) * DHEAD;
    const size_t kvbase = ((size_t)b * LSEQ) * DHEAD;

    stage128(smb + SQH, g_qh + qgbase, tid);
    stage128(smb + SQL, g_ql + qgbase, tid);
    {
        const uint32_t d0 = smb + SBUF0;
        stage64(d0 + OKH, g_kh + kvbase, tid);
        stage64(d0 + OKL, g_kl + kvbase, tid);
        stage64(d0 + OVH, g_vh + kvbase, tid);
        stage64(d0 + OVL, g_vl + kvbase, tid);
    }
    CP_COMMIT();

    // O accum: [at][d-n8 tile][4]  (key-partial: only this warp's keys)
    float o[2][16][4];
    #pragma unroll
    for (int at = 0; at < 2; ++at)
        #pragma unroll
        for (int n = 0; n < 16; ++n) { o[at][n][0] = o[at][n][1] = o[at][n][2] = o[at][n][3] = 0.f; }
    float Z[4] = {0.f, 0.f, 0.f, 0.f};   // row-groups: m0 + qr + 8*rg

    // mask row pointers for the 4 row-groups
    const float* mrow[4];
    #pragma unroll
    for (int rg = 0; rg < 4; ++rg)
        mrow[rg] = MASK + (size_t)(q0 + m0 + qr + 8 * rg) * LSEQ;

    #pragma unroll 1
    for (int kt = 0; kt < NKT; ++kt) {
        if (kt + 1 < NKT) {
            const uint32_t dn = smb + SBUF0 + ((kt + 1) & 1) * BUF_STRIDE;
            const size_t tn = kvbase + (size_t)(kt + 1) * TKN * DHEAD;
            stage64(dn + OKH, g_kh + tn, tid);
            stage64(dn + OKL, g_kl + tn, tid);
            stage64(dn + OVH, g_vh + tn, tid);
            stage64(dn + OVL, g_vl + tn, tid);
            CP_COMMIT();
            asm volatile("cp.async.wait_group 1;" ::: "memory");
        } else {
            asm volatile("cp.async.wait_group 0;" ::: "memory");
        }
        __syncthreads();

        const uint32_t bufb = smb + SBUF0 + (kt & 1) * BUF_STRIDE;
        const uint32_t kh = bufb + OKH, kl = bufb + OKL;
        const uint32_t vh = bufb + OVH, vl = bufb + OVL;

        // ---- S = Qhi*Khi + Qhi*Klo + Qlo*Khi  (rows: 2 m16 tiles; keys: warp's 32) ----
        float c[2][4][4];
        #pragma unroll
        for (int at = 0; at < 2; ++at)
            #pragma unroll
            for (int n = 0; n < 4; ++n) { c[at][n][0] = c[at][n][1] = c[at][n][2] = c[at][n][3] = 0.f; }

        #pragma unroll
        for (int kk = 0; kk < 8; ++kk) {
            uint32_t aH[2][4], aL[2][4];
            ldsm_x4(aH[0], smb + SQH + a_off[0] + kk * 32);
            ldsm_x4(aL[0], smb + SQL + a_off[0] + kk * 32);
            ldsm_x4(aH[1], smb + SQH + a_off[1] + kk * 32);
            ldsm_x4(aL[1], smb + SQL + a_off[1] + kk * 32);
            #pragma unroll
            for (int p = 0; p < 2; ++p) {    // n16 halves of the warp's 32 keys
                const uint32_t toff = (uint32_t)(p * 16 * PAD + kk * 16) * 2;
                uint32_t bH[4], bL[4];
                ldsm_x4(bH, kh + kb4_off + toff);
                ldsm_x4(bL, kl + kb4_off + toff);
                #pragma unroll
                for (int at = 0; at < 2; ++at) {
                    mma16816(c[at][2 * p + 0], aH[at], bH + 0);
                    mma16816(c[at][2 * p + 0], aH[at], bL + 0);
                    mma16816(c[at][2 * p + 0], aL[at], bH + 0);
                    mma16816(c[at][2 * p + 1], aH[at], bH + 2);
                    mma16816(c[at][2 * p + 1], aH[at], bL + 2);
                    mma16816(c[at][2 * p + 1], aL[at], bH + 2);
                }
            }
        }

        // ---- per s-group (16 keys): exp/pack -> PV MMAs ----
        #pragma unroll
        for (int s = 0; s < 2; ++s) {
            uint32_t ph[2][4], pl[2][4];
            #pragma unroll
            for (int at = 0; at < 2; ++at) {
                const float* c0 = c[at][2 * s + 0];
                const float* c1 = c[at][2 * s + 1];
                const int cb0 = kt * TKN + 32 * ng + 8 * (2 * s + 0) + qc2;
                const int cb1 = cb0 + 8;
                const float2 mA0 = *reinterpret_cast<const float2*>(mrow[2 * at + 0] + cb0);
                const float2 mB0 = *reinterpret_cast<const float2*>(mrow[2 * at + 1] + cb0);
                const float2 mA1 = *reinterpret_cast<const float2*>(mrow[2 * at + 0] + cb1);
                const float2 mB1 = *reinterpret_cast<const float2*>(mrow[2 * at + 1] + cb1);
                float e0 = __expf(c0[0] + mA0.x), e1 = __expf(c0[1] + mA0.y);
                float e2 = __expf(c0[2] + mB0.x), e3 = __expf(c0[3] + mB0.y);
                float f0 = __expf(c1[0] + mA1.x), f1 = __expf(c1[1] + mA1.y);
                float f2 = __expf(c1[2] + mB1.x), f3 = __expf(c1[3] + mB1.y);
                Z[2 * at + 0] += (e0 + e1) + (f0 + f1);
                Z[2 * at + 1] += (e2 + e3) + (f2 + f3);
                __nv_bfloat16 h0 = __float2bfloat16_rn(e0), h1 = __float2bfloat16_rn(e1);
                __nv_bfloat16 h2 = __float2bfloat16_rn(e2), h3 = __float2bfloat16_rn(e3);
                __nv_bfloat16 g0 = __float2bfloat16_rn(f0), g1 = __float2bfloat16_rn(f1);
                __nv_bfloat16 g2 = __float2bfloat16_rn(f2), g3 = __float2bfloat16_rn(f3);
                ph[at][0] = pack2(h0, h1);
                ph[at][1] = pack2(h2, h3);
                ph[at][2] = pack2(g0, g1);
                ph[at][3] = pack2(g2, g3);
                pl[at][0] = pack2(__float2bfloat16_rn(e0 - __bfloat162float(h0)),
                                  __float2bfloat16_rn(e1 - __bfloat162float(h1)));
                pl[at][1] = pack2(__float2bfloat16_rn(e2 - __bfloat162float(h2)),
                                  __float2bfloat16_rn(e3 - __bfloat162float(h3)));
                pl[at][2] = pack2(__float2bfloat16_rn(f0 - __bfloat162float(g0)),
                                  __float2bfloat16_rn(f1 - __bfloat162float(g1)));
                pl[at][3] = pack2(__float2bfloat16_rn(f2 - __bfloat162float(g2)),
                                  __float2bfloat16_rn(f3 - __bfloat162float(g3)));
            }
            // PV: O += Phi*Vhi + Plo*Vhi + Phi*Vlo over this s-group
            #pragma unroll
            for (int dp = 0; dp < 8; ++dp) {
                const uint32_t toff = (uint32_t)(s * 16 * PAD + dp * 16) * 2;
                uint32_t bH[4], bL[4];
                ldsm_x4_t(bH, vh + vb4_off + toff);
                ldsm_x4_t(bL, vl + vb4_off + toff);
                #pragma unroll
                for (int at = 0; at < 2; ++at) {
                    mma16816(o[at][2 * dp + 0], ph[at], bH + 0);
                    mma16816(o[at][2 * dp + 0], pl[at], bH + 0);
                    mma16816(o[at][2 * dp + 0], ph[at], bL + 0);
                    mma16816(o[at][2 * dp + 1], ph[at], bH + 2);
                    mma16816(o[at][2 * dp + 1], pl[at], bH + 2);
                    mma16816(o[at][2 * dp + 1], ph[at], bL + 2);
                }
            }
        }
        __syncthreads();
    }

    // ---- quad-reduce Z (lanes sharing rows) ----
    #pragma unroll
    for (int rg = 0; rg < 4; ++rg) {
        Z[rg] += __shfl_xor_sync(0xffffffffu, Z[rg], 1);
        Z[rg] += __shfl_xor_sync(0xffffffffu, Z[rg], 2);
    }

    // ---- cross-warp reduction of key-partial O and Z (ng=1 -> smem -> ng=0) ----
    float* sO = reinterpret_cast<float*>(sm);                 // [4 mg][32 lanes][128]
    float* sZ = reinterpret_cast<float*>(sm + 64 * 1024);     // [4 mg][32 lanes][4]
    const int lane_base = (mg * 32 + l);
    if (ng == 1) {
        float* dst = sO + lane_base * 128;
        #pragma unroll
        for (int at = 0; at < 2; ++at)
            #pragma unroll
            for (int n = 0; n < 16; ++n)
                *reinterpret_cast<float4*>(dst + (at * 16 + n) * 4) =
                    make_float4(o[at][n][0], o[at][n][1], o[at][n][2], o[at][n][3]);
        *reinterpret_cast<float4*>(sZ + lane_base * 4) = make_float4(Z[0], Z[1], Z[2], Z[3]);
    }
    __syncthreads();
    if (ng == 1) return;

    {
        const float* src = sO + lane_base * 128;
        #pragma unroll
        for (int at = 0; at < 2; ++at)
            #pragma unroll
            for (int n = 0; n < 16; ++n) {
                float4 p = *reinterpret_cast<const float4*>(src + (at * 16 + n) * 4);
                o[at][n][0] += p.x; o[at][n][1] += p.y; o[at][n][2] += p.z; o[at][n][3] += p.w;
            }
        float4 zp = *reinterpret_cast<const float4*>(sZ + lane_base * 4);
        Z[0] += zp.x; Z[1] += zp.y; Z[2] += zp.z; Z[3] += zp.w;
    }

    // ---- LayerNorm per row-group; write ----
    #pragma unroll
    for (int rg = 0; rg < 4; ++rg) {
        const int at = rg >> 1, ih = (rg & 1) * 2;
        const float zi = 1.0f / Z[rg];
        float s1 = 0.f, s2 = 0.f;
        #pragma unroll
        for (int n = 0; n < 16; ++n) {
            float x0 = o[at][n][ih + 0] * zi, x1 = o[at][n][ih + 1] * zi;
            s1 += x0 + x1;
            s2 += x0 * x0 + x1 * x1;
        }
        s1 += __shfl_xor_sync(0xffffffffu, s1, 1); s1 += __shfl_xor_sync(0xffffffffu, s1, 2);
        s2 += __shfl_xor_sync(0xffffffffu, s2, 1); s2 += __shfl_xor_sync(0xffffffffu, s2, 2);
        const float mu = s1 * (1.0f / 128.0f);
        const float va = fmaxf(s2 * (1.0f / 128.0f) - mu * mu, 0.0f);
        const float rs = rsqrtf(va + 1e-5f);
        float* orow = OUT + ((size_t)(b * LSEQ + q0 + m0 + qr + 8 * rg)) * DHEAD;
        #pragma unroll
        for (int n = 0; n < 16; ++n) {
            const int cb = 8 * n + qc2;
            const float2 g2 = *reinterpret_cast<const float2*>(GAMMA + cb);
            const float2 b2 = *reinterpret_cast<const float2*>(BETA + cb);
            float2 y;
            y.x = (o[at][n][ih + 0] * zi - mu) * rs * g2.x + b2.x;
            y.y = (o[at][n][ih + 1] * zi - mu) * rs * g2.y + b2.y;
            *reinterpret_cast<float2*>(orow + cb) = y;
        }
    }
}

extern "C" void kernel_launch(void* const* d_in, const int* in_sizes, int n_in,
                              void* d_out, int out_size) {
    (void)in_sizes; (void)n_in; (void)out_size;
    const float* q     = (const float*)d_in[0];
    const float* k     = (const float*)d_in[1];
    const float* v     = (const float*)d_in[2];
    const float* mask  = (const float*)d_in[3];
    const float* gamma = (const float*)d_in[4];
    const float* beta  = (const float*)d_in[5];
    float* out = (float*)d_out;

    cudaFuncSetAttribute(fmha_ln_hmma, cudaFuncAttributeMaxDynamicSharedMemorySize, SMEM_BYTES);

    const int total_f4 = BATCH * LSEQ * DHEAD / 4;
    prep_split<<<total_f4 / 256, 256>>>(q, k, v);
    fmha_ln_hmma<<<dim3(LSEQ / TQ, BATCH), 256, SMEM_BYTES>>>(mask, gamma, beta, out);
}

// round 9
// speedup vs baseline: 1.0933x; 1.0933x over previous
#include <cuda_runtime.h>
#include <cuda_bf16.h>
#include <stdint.h>

// R9 = R6 base + MMA issue reordering to break accumulator RAW chains.
// S-phase: preload 4 p-groups of K frags, issue MMAs pass-major (reuse dist 8).
// PV-phase: dp-quads, preload 8 V frags, pass-major (reuse dist 8).

static constexpr int BATCH = 16;
static constexpr int LSEQ  = 2048;
static constexpr int DHEAD = 128;
static constexpr int TQ    = 128;
static constexpr int TKN   = 64;
static constexpr int NKT   = LSEQ / TKN;   // 32

static constexpr int PAD   = 136;
static constexpr int QT_BYTES = TQ  * PAD * 2;
static constexpr int KT_BYTES = TKN * PAD * 2;
static constexpr int SQH = 0;
static constexpr int SQL = QT_BYTES;
static constexpr int SBUF0 = 2 * QT_BYTES;
static constexpr int BUF_STRIDE = 4 * KT_BYTES;
static constexpr int OKH = 0, OKL = KT_BYTES, OVH = 2 * KT_BYTES, OVL = 3 * KT_BYTES;
static constexpr int SMEM_BYTES = SBUF0 + 2 * BUF_STRIDE;  // 208896

__device__ __align__(16) __nv_bfloat16 g_qh[(size_t)BATCH * LSEQ * DHEAD];
__device__ __align__(16) __nv_bfloat16 g_ql[(size_t)BATCH * LSEQ * DHEAD];
__device__ __align__(16) __nv_bfloat16 g_kh[(size_t)BATCH * LSEQ * DHEAD];
__device__ __align__(16) __nv_bfloat16 g_kl[(size_t)BATCH * LSEQ * DHEAD];
__device__ __align__(16) __nv_bfloat16 g_vh[(size_t)BATCH * LSEQ * DHEAD];
__device__ __align__(16) __nv_bfloat16 g_vl[(size_t)BATCH * LSEQ * DHEAD];

// ---------------- helpers ----------------
__device__ __forceinline__ uint32_t smem_u32(const void* p) {
    uint32_t a;
    asm("{ .reg .u64 t; cvta.to.shared.u64 t, %1; cvt.u32.u64 %0, t; }" : "=r"(a) : "l"(p));
    return a;
}
__device__ __forceinline__ uint32_t pack2(__nv_bfloat16 a, __nv_bfloat16 b) {
    return (uint32_t)__bfloat16_as_ushort(a) | ((uint32_t)__bfloat16_as_ushort(b) << 16);
}
__device__ __forceinline__ void ldsm_x4(uint32_t* r, uint32_t addr) {
    asm volatile("ldmatrix.sync.aligned.m8n8.x4.shared.b16 {%0,%1,%2,%3}, [%4];"
                 : "=r"(r[0]), "=r"(r[1]), "=r"(r[2]), "=r"(r[3]) : "r"(addr));
}
__device__ __forceinline__ void ldsm_x4_t(uint32_t* r, uint32_t addr) {
    asm volatile("ldmatrix.sync.aligned.m8n8.x4.trans.shared.b16 {%0,%1,%2,%3}, [%4];"
                 : "=r"(r[0]), "=r"(r[1]), "=r"(r[2]), "=r"(r[3]) : "r"(addr));
}
__device__ __forceinline__ void mma16816(float* d, const uint32_t* a, const uint32_t* b) {
    asm volatile("mma.sync.aligned.m16n8k16.row.col.f32.bf16.bf16.f32 "
                 "{%0,%1,%2,%3}, {%4,%5,%6,%7}, {%8,%9}, {%0,%1,%2,%3};"
                 : "+f"(d[0]), "+f"(d[1]), "+f"(d[2]), "+f"(d[3])
                 : "r"(a[0]), "r"(a[1]), "r"(a[2]), "r"(a[3]), "r"(b[0]), "r"(b[1]));
}
__device__ __forceinline__ void cp16(uint32_t dst, const void* src) {
    asm volatile("cp.async.cg.shared.global [%0], [%1], 16;" :: "r"(dst), "l"(src));
}
#define CP_COMMIT() asm volatile("cp.async.commit_group;" ::: "memory")

__device__ __forceinline__ void stage64(uint32_t dstb, const __nv_bfloat16* __restrict__ g, int tid) {
    #pragma unroll
    for (int i = 0; i < 4; ++i) {
        int idx = tid + i * 256;
        int row = idx >> 4, c = idx & 15;
        cp16(dstb + row * (PAD * 2) + c * 16, g + row * DHEAD + c * 8);
    }
}
__device__ __forceinline__ void stage128(uint32_t dstb, const __nv_bfloat16* __restrict__ g, int tid) {
    #pragma unroll
    for (int i = 0; i < 8; ++i) {
        int idx = tid + i * 256;
        int row = idx >> 4, c = idx & 15;
        cp16(dstb + row * (PAD * 2) + c * 16, g + row * DHEAD + c * 8);
    }
}

// -------- prep: fp32 -> bf16 hi/lo --------
__device__ __forceinline__ void split4(float4 f, __nv_bfloat16* hi, __nv_bfloat16* lo, size_t i4) {
    __nv_bfloat16 h0 = __float2bfloat16_rn(f.x), h1 = __float2bfloat16_rn(f.y);
    __nv_bfloat16 h2 = __float2bfloat16_rn(f.z), h3 = __float2bfloat16_rn(f.w);
    *reinterpret_cast<uint2*>(hi + 4 * i4) = make_uint2(pack2(h0, h1), pack2(h2, h3));
    *reinterpret_cast<uint2*>(lo + 4 * i4) = make_uint2(
        pack2(__float2bfloat16_rn(f.x - __bfloat162float(h0)), __float2bfloat16_rn(f.y - __bfloat162float(h1))),
        pack2(__float2bfloat16_rn(f.z - __bfloat162float(h2)), __float2bfloat16_rn(f.w - __bfloat162float(h3))));
}
__global__ void prep_split(const float* __restrict__ q, const float* __restrict__ k,
                           const float* __restrict__ v) {
    size_t i = (size_t)blockIdx.x * blockDim.x + threadIdx.x;
    split4(reinterpret_cast<const float4*>(q)[i], g_qh, g_ql, i);
    split4(reinterpret_cast<const float4*>(k)[i], g_kh, g_kl, i);
    split4(reinterpret_cast<const float4*>(v)[i], g_vh, g_vl, i);
}

// -------- fused attention + layernorm --------
__global__ void __launch_bounds__(256, 1)
fmha_ln_hmma(const float* __restrict__ MASK, const float* __restrict__ GAMMA,
             const float* __restrict__ BETA, float* __restrict__ OUT) {
    extern __shared__ char sm[];
    const int tid = threadIdx.x;
    const int w   = tid >> 5;
    const int l   = tid & 31;
    const int b   = blockIdx.y;
    const int q0  = blockIdx.x * TQ;

    const int qr  = l >> 2;
    const int qc2 = (l & 3) * 2;
    const int r1  = 16 * w + qr;

    const uint32_t smb = smem_u32(sm);

    const int lr = l & 7, g = l >> 3;
    const int a_row = 16 * w + lr + ((g & 1) << 3);
    const uint32_t a_off   = (uint32_t)(a_row * PAD + ((g >> 1) << 3)) * 2;
    const uint32_t kb4_off = (uint32_t)((lr + ((g >> 1) << 3)) * PAD + ((g & 1) << 3)) * 2;
    const uint32_t vb4_off = (uint32_t)((lr + ((g & 1) << 3)) * PAD + ((g >> 1) << 3)) * 2;

    const size_t qgbase = ((size_t)(b * LSEQ + q0)) * DHEAD;
    const size_t kvbase = ((size_t)b * LSEQ) * DHEAD;

    stage128(smb + SQH, g_qh + qgbase, tid);
    stage128(smb + SQL, g_ql + qgbase, tid);
    {
        const uint32_t d0 = smb + SBUF0;
        stage64(d0 + OKH, g_kh + kvbase, tid);
        stage64(d0 + OKL, g_kl + kvbase, tid);
        stage64(d0 + OVH, g_vh + kvbase, tid);
        stage64(d0 + OVL, g_vl + kvbase, tid);
    }
    CP_COMMIT();

    float o[16][4];
    #pragma unroll
    for (int n = 0; n < 16; ++n) { o[n][0] = o[n][1] = o[n][2] = o[n][3] = 0.f; }
    float Z1 = 0.f, Z2 = 0.f;

    const float* mrow1 = MASK + (size_t)(q0 + r1) * LSEQ;
    const float* mrow2 = mrow1 + 8 * LSEQ;

    #pragma unroll 1
    for (int kt = 0; kt < NKT; ++kt) {
        if (kt + 1 < NKT) {
            const uint32_t dn = smb + SBUF0 + ((kt + 1) & 1) * BUF_STRIDE;
            const size_t tn = kvbase + (size_t)(kt + 1) * TKN * DHEAD;
            stage64(dn + OKH, g_kh + tn, tid);
            stage64(dn + OKL, g_kl + tn, tid);
            stage64(dn + OVH, g_vh + tn, tid);
            stage64(dn + OVL, g_vl + tn, tid);
            CP_COMMIT();
            asm volatile("cp.async.wait_group 1;" ::: "memory");
        } else {
            asm volatile("cp.async.wait_group 0;" ::: "memory");
        }
        __syncthreads();

        const uint32_t bufb = smb + SBUF0 + (kt & 1) * BUF_STRIDE;
        const uint32_t kh = bufb + OKH, kl = bufb + OKL;
        const uint32_t vh = bufb + OVH, vl = bufb + OVL;

        // ---- S = Qhi*Khi + Qhi*Klo + Qlo*Khi  (pass-major MMA order) ----
        float c[8][4];
        #pragma unroll
        for (int n = 0; n < 8; ++n) { c[n][0] = c[n][1] = c[n][2] = c[n][3] = 0.f; }

        #pragma unroll
        for (int kk = 0; kk < 8; ++kk) {
            uint32_t aH[4], aL[4];
            ldsm_x4(aH, smb + SQH + a_off + kk * 32);
            ldsm_x4(aL, smb + SQL + a_off + kk * 32);
            // preload all 4 p-groups' K fragments (crossbar streams under MMAs)
            uint32_t bH[4][4], bL[4][4];
            #pragma unroll
            for (int p = 0; p < 4; ++p) {
                const uint32_t toff = (uint32_t)(p * 16 * PAD + kk * 16) * 2;
                ldsm_x4(bH[p], kh + kb4_off + toff);
                ldsm_x4(bL[p], kl + kb4_off + toff);
            }
            // pass-major: same-accumulator reuse distance = 8 MMAs
            #pragma unroll
            for (int p = 0; p < 4; ++p) {
                mma16816(c[2 * p + 0], aH, bH[p] + 0);
                mma16816(c[2 * p + 1], aH, bH[p] + 2);
            }
            #pragma unroll
            for (int p = 0; p < 4; ++p) {
                mma16816(c[2 * p + 0], aH, bL[p] + 0);
                mma16816(c[2 * p + 1], aH, bL[p] + 2);
            }
            #pragma unroll
            for (int p = 0; p < 4; ++p) {
                mma16816(c[2 * p + 0], aL, bH[p] + 0);
                mma16816(c[2 * p + 1], aL, bH[p] + 2);
            }
        }

        // ---- per s-group (16 keys): exp/pack -> PV (dp-quads, pass-major) ----
        #pragma unroll
        for (int s = 0; s < 4; ++s) {
            const float* c0 = c[2 * s + 0];
            const float* c1 = c[2 * s + 1];
            const int cb0 = kt * TKN + 8 * (2 * s + 0) + qc2;
            const int cb1 = cb0 + 8;
            const float2 mA0 = *reinterpret_cast<const float2*>(mrow1 + cb0);
            const float2 mB0 = *reinterpret_cast<const float2*>(mrow2 + cb0);
            const float2 mA1 = *reinterpret_cast<const float2*>(mrow1 + cb1);
            const float2 mB1 = *reinterpret_cast<const float2*>(mrow2 + cb1);
            float e0 = __expf(c0[0] + mA0.x), e1 = __expf(c0[1] + mA0.y);
            float e2 = __expf(c0[2] + mB0.x), e3 = __expf(c0[3] + mB0.y);
            float f0 = __expf(c1[0] + mA1.x), f1 = __expf(c1[1] + mA1.y);
            float f2 = __expf(c1[2] + mB1.x), f3 = __expf(c1[3] + mB1.y);
            Z1 += (e0 + e1) + (f0 + f1);
            Z2 += (e2 + e3) + (f2 + f3);
            __nv_bfloat16 h0 = __float2bfloat16_rn(e0), h1 = __float2bfloat16_rn(e1);
            __nv_bfloat16 h2 = __float2bfloat16_rn(e2), h3 = __float2bfloat16_rn(e3);
            __nv_bfloat16 g0 = __float2bfloat16_rn(f0), g1 = __float2bfloat16_rn(f1);
            __nv_bfloat16 g2 = __float2bfloat16_rn(f2), g3 = __float2bfloat16_rn(f3);
            uint32_t ph[4], pl[4];
            ph[0] = pack2(h0, h1);
            ph[1] = pack2(h2, h3);
            ph[2] = pack2(g0, g1);
            ph[3] = pack2(g2, g3);
            pl[0] = pack2(__float2bfloat16_rn(e0 - __bfloat162float(h0)),
                          __float2bfloat16_rn(e1 - __bfloat162float(h1)));
            pl[1] = pack2(__float2bfloat16_rn(e2 - __bfloat162float(h2)),
                          __float2bfloat16_rn(e3 - __bfloat162float(h3)));
            pl[2] = pack2(__float2bfloat16_rn(f0 - __bfloat162float(g0)),
                          __float2bfloat16_rn(f1 - __bfloat162float(g1)));
            pl[3] = pack2(__float2bfloat16_rn(f2 - __bfloat162float(g2)),
                          __float2bfloat16_rn(f3 - __bfloat162float(g3)));

            // PV over dp-quads: preload 8 V frags, then 24 MMAs pass-major
            #pragma unroll
            for (int dq = 0; dq < 2; ++dq) {
                uint32_t vH[4][4], vL[4][4];
                #pragma unroll
                for (int i = 0; i < 4; ++i) {
                    const int dp = 4 * dq + i;
                    const uint32_t toff = (uint32_t)(s * 16 * PAD + dp * 16) * 2;
                    ldsm_x4_t(vH[i], vh + vb4_off + toff);
                    ldsm_x4_t(vL[i], vl + vb4_off + toff);
                }
                #pragma unroll
                for (int i = 0; i < 4; ++i) {
                    const int dp = 4 * dq + i;
                    mma16816(o[2 * dp + 0], ph, vH[i] + 0);
                    mma16816(o[2 * dp + 1], ph, vH[i] + 2);
                }
                #pragma unroll
                for (int i = 0; i < 4; ++i) {
                    const int dp = 4 * dq + i;
                    mma16816(o[2 * dp + 0], pl, vH[i] + 0);
                    mma16816(o[2 * dp + 1], pl, vH[i] + 2);
                }
                #pragma unroll
                for (int i = 0; i < 4; ++i) {
                    const int dp = 4 * dq + i;
                    mma16816(o[2 * dp + 0], ph, vL[i] + 0);
                    mma16816(o[2 * dp + 1], ph, vL[i] + 2);
                }
            }
        }
        __syncthreads();
    }

    // ---- quad-reduce Z; LayerNorm; write ----
    Z1 += __shfl_xor_sync(0xffffffffu, Z1, 1);
    Z1 += __shfl_xor_sync(0xffffffffu, Z1, 2);
    Z2 += __shfl_xor_sync(0xffffffffu, Z2, 1);
    Z2 += __shfl_xor_sync(0xffffffffu, Z2, 2);
    const float zi1 = 1.0f / Z1, zi2 = 1.0f / Z2;

    float s1a = 0.f, s1b = 0.f, s2a = 0.f, s2b = 0.f;
    #pragma unroll
    for (int n = 0; n < 16; ++n) {
        float x0 = o[n][0] * zi1, x1 = o[n][1] * zi1;
        float x2 = o[n][2] * zi2, x3 = o[n][3] * zi2;
        s1a += x0 + x1;  s1b += x0 * x0 + x1 * x1;
        s2a += x2 + x3;  s2b += x2 * x2 + x3 * x3;
    }
    s1a += __shfl_xor_sync(0xffffffffu, s1a, 1); s1a += __shfl_xor_sync(0xffffffffu, s1a, 2);
    s1b += __shfl_xor_sync(0xffffffffu, s1b, 1); s1b += __shfl_xor_sync(0xffffffffu, s1b, 2);
    s2a += __shfl_xor_sync(0xffffffffu, s2a, 1); s2a += __shfl_xor_sync(0xffffffffu, s2a, 2);
    s2b += __shfl_xor_sync(0xffffffffu, s2b, 1); s2b += __shfl_xor_sync(0xffffffffu, s2b, 2);

    const float mu1 = s1a * (1.0f / 128.0f);
    const float v1  = fmaxf(s1b * (1.0f / 128.0f) - mu1 * mu1, 0.0f);
    const float rs1 = rsqrtf(v1 + 1e-5f);
    const float mu2 = s2a * (1.0f / 128.0f);
    const float v2  = fmaxf(s2b * (1.0f / 128.0f) - mu2 * mu2, 0.0f);
    const float rs2 = rsqrtf(v2 + 1e-5f);

    float* orow1 = OUT + ((size_t)(b * LSEQ + q0 + r1)) * DHEAD;
    float* orow2 = orow1 + 8 * DHEAD;
    #pragma unroll
    for (int n = 0; n < 16; ++n) {
        const int cb = 8 * n + qc2;
        const float2 g2 = *reinterpret_cast<const float2*>(GAMMA + cb);
        const float2 b2 = *reinterpret_cast<const float2*>(BETA + cb);
        float2 y1, y2;
        y1.x = (o[n][0] * zi1 - mu1) * rs1 * g2.x + b2.x;
        y1.y = (o[n][1] * zi1 - mu1) * rs1 * g2.y + b2.y;
        y2.x = (o[n][2] * zi2 - mu2) * rs2 * g2.x + b2.x;
        y2.y = (o[n][3] * zi2 - mu2) * rs2 * g2.y + b2.y;
        *reinterpret_cast<float2*>(orow1 + cb) = y1;
        *reinterpret_cast<float2*>(orow2 + cb) = y2;
    }
}

extern "C" void kernel_launch(void* const* d_in, const int* in_sizes, int n_in,
                              void* d_out, int out_size) {
    (void)in_sizes; (void)n_in; (void)out_size;
    const float* q     = (const float*)d_in[0];
    const float* k     = (const float*)d_in[1];
    const float* v     = (const float*)d_in[2];
    const float* mask  = (const float*)d_in[3];
    const float* gamma = (const float*)d_in[4];
    const float* beta  = (const float*)d_in[5];
    float* out = (float*)d_out;

    cudaFuncSetAttribute(fmha_ln_hmma, cudaFuncAttributeMaxDynamicSharedMemorySize, SMEM_BYTES);

    const int total_f4 = BATCH * LSEQ * DHEAD / 4;
    prep_split<<<total_f4 / 256, 256>>>(q, k, v);
    fmha_ln_hmma<<<dim3(LSEQ / TQ, BATCH), 256, SMEM_BYTES>>>(mask, gamma, beta, out);
}

// round 10
// speedup vs baseline: 1.0966x; 1.0030x over previous
#include <cuda_runtime.h>
#include <cuda_bf16.h>
#include <stdint.h>

// R10 = R9 + decoupled LDSM/MMA streams:
//  - Q fragments persistent in registers (loaded once, no A-LDSM in loop)
//  - S-phase: double-buffered K-frag registers, loads of kk+1 under MMAs of kk
//  - PV-phase: exp/pack all s-groups, then pipelined V-frag double buffer

static constexpr int BATCH = 16;
static constexpr int LSEQ  = 2048;
static constexpr int DHEAD = 128;
static constexpr int TQ    = 128;
static constexpr int TKN   = 64;
static constexpr int NKT   = LSEQ / TKN;   // 32

static constexpr int PAD   = 136;
static constexpr int QT_BYTES = TQ  * PAD * 2;
static constexpr int KT_BYTES = TKN * PAD * 2;
static constexpr int SQH = 0;
static constexpr int SQL = QT_BYTES;
static constexpr int SBUF0 = 2 * QT_BYTES;
static constexpr int BUF_STRIDE = 4 * KT_BYTES;
static constexpr int OKH = 0, OKL = KT_BYTES, OVH = 2 * KT_BYTES, OVL = 3 * KT_BYTES;
static constexpr int SMEM_BYTES = SBUF0 + 2 * BUF_STRIDE;  // 208896

__device__ __align__(16) __nv_bfloat16 g_qh[(size_t)BATCH * LSEQ * DHEAD];
__device__ __align__(16) __nv_bfloat16 g_ql[(size_t)BATCH * LSEQ * DHEAD];
__device__ __align__(16) __nv_bfloat16 g_kh[(size_t)BATCH * LSEQ * DHEAD];
__device__ __align__(16) __nv_bfloat16 g_kl[(size_t)BATCH * LSEQ * DHEAD];
__device__ __align__(16) __nv_bfloat16 g_vh[(size_t)BATCH * LSEQ * DHEAD];
__device__ __align__(16) __nv_bfloat16 g_vl[(size_t)BATCH * LSEQ * DHEAD];

// ---------------- helpers ----------------
__device__ __forceinline__ uint32_t smem_u32(const void* p) {
    uint32_t a;
    asm("{ .reg .u64 t; cvta.to.shared.u64 t, %1; cvt.u32.u64 %0, t; }" : "=r"(a) : "l"(p));
    return a;
}
__device__ __forceinline__ uint32_t pack2(__nv_bfloat16 a, __nv_bfloat16 b) {
    return (uint32_t)__bfloat16_as_ushort(a) | ((uint32_t)__bfloat16_as_ushort(b) << 16);
}
__device__ __forceinline__ void ldsm_x4(uint32_t* r, uint32_t addr) {
    asm volatile("ldmatrix.sync.aligned.m8n8.x4.shared.b16 {%0,%1,%2,%3}, [%4];"
                 : "=r"(r[0]), "=r"(r[1]), "=r"(r[2]), "=r"(r[3]) : "r"(addr));
}
__device__ __forceinline__ void ldsm_x4_t(uint32_t* r, uint32_t addr) {
    asm volatile("ldmatrix.sync.aligned.m8n8.x4.trans.shared.b16 {%0,%1,%2,%3}, [%4];"
                 : "=r"(r[0]), "=r"(r[1]), "=r"(r[2]), "=r"(r[3]) : "r"(addr));
}
__device__ __forceinline__ void mma16816(float* d, const uint32_t* a, const uint32_t* b) {
    asm volatile("mma.sync.aligned.m16n8k16.row.col.f32.bf16.bf16.f32 "
                 "{%0,%1,%2,%3}, {%4,%5,%6,%7}, {%8,%9}, {%0,%1,%2,%3};"
                 : "+f"(d[0]), "+f"(d[1]), "+f"(d[2]), "+f"(d[3])
                 : "r"(a[0]), "r"(a[1]), "r"(a[2]), "r"(a[3]), "r"(b[0]), "r"(b[1]));
}
__device__ __forceinline__ void cp16(uint32_t dst, const void* src) {
    asm volatile("cp.async.cg.shared.global [%0], [%1], 16;" :: "r"(dst), "l"(src));
}
#define CP_COMMIT() asm volatile("cp.async.commit_group;" ::: "memory")

__device__ __forceinline__ void stage64(uint32_t dstb, const __nv_bfloat16* __restrict__ g, int tid) {
    #pragma unroll
    for (int i = 0; i < 4; ++i) {
        int idx = tid + i * 256;
        int row = idx >> 4, c = idx & 15;
        cp16(dstb + row * (PAD * 2) + c * 16, g + row * DHEAD + c * 8);
    }
}
__device__ __forceinline__ void stage128(uint32_t dstb, const __nv_bfloat16* __restrict__ g, int tid) {
    #pragma unroll
    for (int i = 0; i < 8; ++i) {
        int idx = tid + i * 256;
        int row = idx >> 4, c = idx & 15;
        cp16(dstb + row * (PAD * 2) + c * 16, g + row * DHEAD + c * 8);
    }
}

// -------- prep: fp32 -> bf16 hi/lo --------
__device__ __forceinline__ void split4(float4 f, __nv_bfloat16* hi, __nv_bfloat16* lo, size_t i4) {
    __nv_bfloat16 h0 = __float2bfloat16_rn(f.x), h1 = __float2bfloat16_rn(f.y);
    __nv_bfloat16 h2 = __float2bfloat16_rn(f.z), h3 = __float2bfloat16_rn(f.w);
    *reinterpret_cast<uint2*>(hi + 4 * i4) = make_uint2(pack2(h0, h1), pack2(h2, h3));
    *reinterpret_cast<uint2*>(lo + 4 * i4) = make_uint2(
        pack2(__float2bfloat16_rn(f.x - __bfloat162float(h0)), __float2bfloat16_rn(f.y - __bfloat162float(h1))),
        pack2(__float2bfloat16_rn(f.z - __bfloat162float(h2)), __float2bfloat16_rn(f.w - __bfloat162float(h3))));
}
__global__ void prep_split(const float* __restrict__ q, const float* __restrict__ k,
                           const float* __restrict__ v) {
    size_t i = (size_t)blockIdx.x * blockDim.x + threadIdx.x;
    split4(reinterpret_cast<const float4*>(q)[i], g_qh, g_ql, i);
    split4(reinterpret_cast<const float4*>(k)[i], g_kh, g_kl, i);
    split4(reinterpret_cast<const float4*>(v)[i], g_vh, g_vl, i);
}

// -------- fused attention + layernorm --------
__global__ void __launch_bounds__(256, 1)
fmha_ln_hmma(const float* __restrict__ MASK, const float* __restrict__ GAMMA,
             const float* __restrict__ BETA, float* __restrict__ OUT) {
    extern __shared__ char sm[];
    const int tid = threadIdx.x;
    const int w   = tid >> 5;
    const int l   = tid & 31;
    const int b   = blockIdx.y;
    const int q0  = blockIdx.x * TQ;

    const int qr  = l >> 2;
    const int qc2 = (l & 3) * 2;
    const int r1  = 16 * w + qr;

    const uint32_t smb = smem_u32(sm);

    const int lr = l & 7, g = l >> 3;
    const int a_row = 16 * w + lr + ((g & 1) << 3);
    const uint32_t a_off   = (uint32_t)(a_row * PAD + ((g >> 1) << 3)) * 2;
    const uint32_t kb4_off = (uint32_t)((lr + ((g >> 1) << 3)) * PAD + ((g & 1) << 3)) * 2;
    const uint32_t vb4_off = (uint32_t)((lr + ((g & 1) << 3)) * PAD + ((g >> 1) << 3)) * 2;

    const size_t qgbase = ((size_t)(b * LSEQ + q0)) * DHEAD;
    const size_t kvbase = ((size_t)b * LSEQ) * DHEAD;

    stage128(smb + SQH, g_qh + qgbase, tid);
    stage128(smb + SQL, g_ql + qgbase, tid);
    CP_COMMIT();
    {
        const uint32_t d0 = smb + SBUF0;
        stage64(d0 + OKH, g_kh + kvbase, tid);
        stage64(d0 + OKL, g_kl + kvbase, tid);
        stage64(d0 + OVH, g_vh + kvbase, tid);
        stage64(d0 + OVL, g_vl + kvbase, tid);
    }
    CP_COMMIT();

    // ---- persistent Q fragments (loaded once; no A-LDSM in the main loop) ----
    uint32_t qH[8][4], qL[8][4];
    asm volatile("cp.async.wait_group 1;" ::: "memory");   // Q staged
    __syncthreads();
    #pragma unroll
    for (int kk = 0; kk < 8; ++kk) {
        ldsm_x4(qH[kk], smb + SQH + a_off + kk * 32);
        ldsm_x4(qL[kk], smb + SQL + a_off + kk * 32);
    }

    float o[16][4];
    #pragma unroll
    for (int n = 0; n < 16; ++n) { o[n][0] = o[n][1] = o[n][2] = o[n][3] = 0.f; }
    float Z1 = 0.f, Z2 = 0.f;

    const float* mrow1 = MASK + (size_t)(q0 + r1) * LSEQ;
    const float* mrow2 = mrow1 + 8 * LSEQ;

    #pragma unroll 1
    for (int kt = 0; kt < NKT; ++kt) {
        if (kt + 1 < NKT) {
            const uint32_t dn = smb + SBUF0 + ((kt + 1) & 1) * BUF_STRIDE;
            const size_t tn = kvbase + (size_t)(kt + 1) * TKN * DHEAD;
            stage64(dn + OKH, g_kh + tn, tid);
            stage64(dn + OKL, g_kl + tn, tid);
            stage64(dn + OVH, g_vh + tn, tid);
            stage64(dn + OVL, g_vl + tn, tid);
            CP_COMMIT();
            asm volatile("cp.async.wait_group 1;" ::: "memory");
        } else {
            asm volatile("cp.async.wait_group 0;" ::: "memory");
        }
        __syncthreads();

        const uint32_t bufb = smb + SBUF0 + (kt & 1) * BUF_STRIDE;
        const uint32_t kh = bufb + OKH, kl = bufb + OKL;
        const uint32_t vh = bufb + OVH, vl = bufb + OVL;

        // ---- S = Qhi*Khi + Qhi*Klo + Qlo*Khi  (K-frag register pipeline) ----
        float c[8][4];
        #pragma unroll
        for (int n = 0; n < 8; ++n) { c[n][0] = c[n][1] = c[n][2] = c[n][3] = 0.f; }

        uint32_t bH[2][4][4], bL[2][4][4];
        #pragma unroll
        for (int p = 0; p < 4; ++p) {                 // preload kk=0
            const uint32_t toff = (uint32_t)(p * 16 * PAD) * 2;
            ldsm_x4(bH[0][p], kh + kb4_off + toff);
            ldsm_x4(bL[0][p], kl + kb4_off + toff);
        }
        #pragma unroll
        for (int kk = 0; kk < 8; ++kk) {
            const int cur = kk & 1;
            if (kk < 7) {                              // stream kk+1 under kk's MMAs
                #pragma unroll
                for (int p = 0; p < 4; ++p) {
                    const uint32_t toff = (uint32_t)(p * 16 * PAD + (kk + 1) * 16) * 2;
                    ldsm_x4(bH[cur ^ 1][p], kh + kb4_off + toff);
                    ldsm_x4(bL[cur ^ 1][p], kl + kb4_off + toff);
                }
            }
            #pragma unroll
            for (int p = 0; p < 4; ++p) {
                mma16816(c[2 * p + 0], qH[kk], bH[cur][p] + 0);
                mma16816(c[2 * p + 1], qH[kk], bH[cur][p] + 2);
            }
            #pragma unroll
            for (int p = 0; p < 4; ++p) {
                mma16816(c[2 * p + 0], qH[kk], bL[cur][p] + 0);
                mma16816(c[2 * p + 1], qH[kk], bL[cur][p] + 2);
            }
            #pragma unroll
            for (int p = 0; p < 4; ++p) {
                mma16816(c[2 * p + 0], qL[kk], bH[cur][p] + 0);
                mma16816(c[2 * p + 1], qL[kk], bH[cur][p] + 2);
            }
        }

        // ---- exp/pack ALL s-groups (c -> P, register-neutral) ----
        uint32_t ph[4][4], pl[4][4];
        #pragma unroll
        for (int s = 0; s < 4; ++s) {
            const float* c0 = c[2 * s + 0];
            const float* c1 = c[2 * s + 1];
            const int cb0 = kt * TKN + 16 * s + qc2;
            const int cb1 = cb0 + 8;
            const float2 mA0 = *reinterpret_cast<const float2*>(mrow1 + cb0);
            const float2 mB0 = *reinterpret_cast<const float2*>(mrow2 + cb0);
            const float2 mA1 = *reinterpret_cast<const float2*>(mrow1 + cb1);
            const float2 mB1 = *reinterpret_cast<const float2*>(mrow2 + cb1);
            float e0 = __expf(c0[0] + mA0.x), e1 = __expf(c0[1] + mA0.y);
            float e2 = __expf(c0[2] + mB0.x), e3 = __expf(c0[3] + mB0.y);
            float f0 = __expf(c1[0] + mA1.x), f1 = __expf(c1[1] + mA1.y);
            float f2 = __expf(c1[2] + mB1.x), f3 = __expf(c1[3] + mB1.y);
            Z1 += (e0 + e1) + (f0 + f1);
            Z2 += (e2 + e3) + (f2 + f3);
            __nv_bfloat16 h0 = __float2bfloat16_rn(e0), h1 = __float2bfloat16_rn(e1);
            __nv_bfloat16 h2 = __float2bfloat16_rn(e2), h3 = __float2bfloat16_rn(e3);
            __nv_bfloat16 g0 = __float2bfloat16_rn(f0), g1 = __float2bfloat16_rn(f1);
            __nv_bfloat16 g2 = __float2bfloat16_rn(f2), g3 = __float2bfloat16_rn(f3);
            ph[s][0] = pack2(h0, h1);
            ph[s][1] = pack2(h2, h3);
            ph[s][2] = pack2(g0, g1);
            ph[s][3] = pack2(g2, g3);
            pl[s][0] = pack2(__float2bfloat16_rn(e0 - __bfloat162float(h0)),
                             __float2bfloat16_rn(e1 - __bfloat162float(h1)));
            pl[s][1] = pack2(__float2bfloat16_rn(e2 - __bfloat162float(h2)),
                             __float2bfloat16_rn(e3 - __bfloat162float(h3)));
            pl[s][2] = pack2(__float2bfloat16_rn(f0 - __bfloat162float(g0)),
                             __float2bfloat16_rn(f1 - __bfloat162float(g1)));
            pl[s][3] = pack2(__float2bfloat16_rn(f2 - __bfloat162float(g2)),
                             __float2bfloat16_rn(f3 - __bfloat162float(g3)));
        }

        // ---- PV: V-frag register pipeline over 8 steps (s,dq) ----
        uint32_t vH[2][4][4], vL[2][4][4];
        #pragma unroll
        for (int i = 0; i < 4; ++i) {                 // preload step 0 (s=0,dq=0)
            const uint32_t toff = (uint32_t)(i * 16) * 2;
            ldsm_x4_t(vH[0][i], vh + vb4_off + toff);
            ldsm_x4_t(vL[0][i], vl + vb4_off + toff);
        }
        #pragma unroll
        for (int j = 0; j < 8; ++j) {
            const int jb = j & 1;
            if (j < 7) {                               // stream step j+1
                const int sn = (j + 1) >> 1, dqn = (j + 1) & 1;
                #pragma unroll
                for (int i = 0; i < 4; ++i) {
                    const uint32_t toff = (uint32_t)(sn * 16 * PAD + (4 * dqn + i) * 16) * 2;
                    ldsm_x4_t(vH[jb ^ 1][i], vh + vb4_off + toff);
                    ldsm_x4_t(vL[jb ^ 1][i], vl + vb4_off + toff);
                }
            }
            const int s = j >> 1, dq = j & 1;
            #pragma unroll
            for (int i = 0; i < 4; ++i) {
                const int dp = 4 * dq + i;
                mma16816(o[2 * dp + 0], ph[s], vH[jb][i] + 0);
                mma16816(o[2 * dp + 1], ph[s], vH[jb][i] + 2);
            }
            #pragma unroll
            for (int i = 0; i < 4; ++i) {
                const int dp = 4 * dq + i;
                mma16816(o[2 * dp + 0], pl[s], vH[jb][i] + 0);
                mma16816(o[2 * dp + 1], pl[s], vH[jb][i] + 2);
            }
            #pragma unroll
            for (int i = 0; i < 4; ++i) {
                const int dp = 4 * dq + i;
                mma16816(o[2 * dp + 0], ph[s], vL[jb][i] + 0);
                mma16816(o[2 * dp + 1], ph[s], vL[jb][i] + 2);
            }
        }
        __syncthreads();
    }

    // ---- quad-reduce Z; LayerNorm; write ----
    Z1 += __shfl_xor_sync(0xffffffffu, Z1, 1);
    Z1 += __shfl_xor_sync(0xffffffffu, Z1, 2);
    Z2 += __shfl_xor_sync(0xffffffffu, Z2, 1);
    Z2 += __shfl_xor_sync(0xffffffffu, Z2, 2);
    const float zi1 = 1.0f / Z1, zi2 = 1.0f / Z2;

    float s1a = 0.f, s1b = 0.f, s2a = 0.f, s2b = 0.f;
    #pragma unroll
    for (int n = 0; n < 16; ++n) {
        float x0 = o[n][0] * zi1, x1 = o[n][1] * zi1;
        float x2 = o[n][2] * zi2, x3 = o[n][3] * zi2;
        s1a += x0 + x1;  s1b += x0 * x0 + x1 * x1;
        s2a += x2 + x3;  s2b += x2 * x2 + x3 * x3;
    }
    s1a += __shfl_xor_sync(0xffffffffu, s1a, 1); s1a += __shfl_xor_sync(0xffffffffu, s1a, 2);
    s1b += __shfl_xor_sync(0xffffffffu, s1b, 1); s1b += __shfl_xor_sync(0xffffffffu, s1b, 2);
    s2a += __shfl_xor_sync(0xffffffffu, s2a, 1); s2a += __shfl_xor_sync(0xffffffffu, s2a, 2);
    s2b += __shfl_xor_sync(0xffffffffu, s2b, 1); s2b += __shfl_xor_sync(0xffffffffu, s2b, 2);

    const float mu1 = s1a * (1.0f / 128.0f);
    const float v1  = fmaxf(s1b * (1.0f / 128.0f) - mu1 * mu1, 0.0f);
    const float rs1 = rsqrtf(v1 + 1e-5f);
    const float mu2 = s2a * (1.0f / 128.0f);
    const float v2  = fmaxf(s2b * (1.0f / 128.0f) - mu2 * mu2, 0.0f);
    const float rs2 = rsqrtf(v2 + 1e-5f);

    float* orow1 = OUT + ((size_t)(b * LSEQ + q0 + r1)) * DHEAD;
    float* orow2 = orow1 + 8 * DHEAD;
    #pragma unroll
    for (int n = 0; n < 16; ++n) {
        const int cb = 8 * n + qc2;
        const float2 g2 = *reinterpret_cast<const float2*>(GAMMA + cb);
        const float2 b2 = *reinterpret_cast<const float2*>(BETA + cb);
        float2 y1, y2;
        y1.x = (o[n][0] * zi1 - mu1) * rs1 * g2.x + b2.x;
        y1.y = (o[n][1] * zi1 - mu1) * rs1 * g2.y + b2.y;
        y2.x = (o[n][2] * zi2 - mu2) * rs2 * g2.x + b2.x;
        y2.y = (o[n][3] * zi2 - mu2) * rs2 * g2.y + b2.y;
        *reinterpret_cast<float2*>(orow1 + cb) = y1;
        *reinterpret_cast<float2*>(orow2 + cb) = y2;
    }
}

extern "C" void kernel_launch(void* const* d_in, const int* in_sizes, int n_in,
                              void* d_out, int out_size) {
    (void)in_sizes; (void)n_in; (void)out_size;
    const float* q     = (const float*)d_in[0];
    const float* k     = (const float*)d_in[1];
    const float* v     = (const float*)d_in[2];
    const float* mask  = (const float*)d_in[3];
    const float* gamma = (const float*)d_in[4];
    const float* beta  = (const float*)d_in[5];
    float* out = (float*)d_out;

    cudaFuncSetAttribute(fmha_ln_hmma, cudaFuncAttributeMaxDynamicSharedMemorySize, SMEM_BYTES);

    const int total_f4 = BATCH * LSEQ * DHEAD / 4;
    prep_split<<<total_f4 / 256, 256>>>(q, k, v);
    fmha_ln_hmma<<<dim3(LSEQ / TQ, BATCH), 256, SMEM_BYTES>>>(mask, gamma, beta, out);
}